// round 10
// baseline (speedup 1.0000x reference)
#include <cuda_runtime.h>
#include <cuda_bf16.h>
#include <mma.h>
#include <cstdint>
#include <cstddef>

using namespace nvcuda;

#define V_   50000
#define E_   512
#define H_   1024
#define S_   512
#define B_   64
#define NT_  13
#define G_   4096   // 4*H
#define DFF_ 256

// ---------------- static device scratch (no allocations allowed) ----------------
__device__ __nv_bfloat16 g_Wih[(size_t)NT_ * G_ * E_];   // bf16 input weights
__device__ __nv_bfloat16 g_Whh[(size_t)NT_ * G_ * H_];   // bf16 recurrent weights
__device__ float         g_bias[NT_ * G_];               // b_ih + b_hh
__device__ __nv_bfloat16 g_Xbf[(size_t)S_ * B_ * E_];    // gathered embeddings, bf16
// Xp layout: [t][cc][b][64]  (cc = recur CTA = h-col group; 64 cols = q*16+j, q=i/f/g/o)
__device__ float         g_Xp[(size_t)S_ * 64 * B_ * 64];
__device__ __nv_bfloat16 g_h[2][B_ * H_];                // double-buffered hidden state
__device__ float         g_hf[B_ * H_];                  // final hidden, fp32 for MLP
__device__ unsigned      g_flags[64 * 32];               // per-CTA step flags (128B padded)

// ---------------- helpers ----------------
__device__ __forceinline__ unsigned ld_acquire(const unsigned* p) {
    unsigned v;
    asm volatile("ld.acquire.gpu.u32 %0, [%1];" : "=r"(v) : "l"(p) : "memory");
    return v;
}
__device__ __forceinline__ void st_release(unsigned* p, unsigned v) {
    asm volatile("st.release.gpu.u32 [%0], %1;" :: "l"(p), "r"(v) : "memory");
}
// L2-only (cg) async copy: avoids stale-L1 hazards on cross-SM h traffic and L1 pollution.
__device__ __forceinline__ void cp_async16_cg(void* dst_smem, const void* src) {
    unsigned d = (unsigned)__cvta_generic_to_shared(dst_smem);
    asm volatile("cp.async.cg.shared.global [%0], [%1], 16;" :: "r"(d), "l"(src));
}
__device__ __forceinline__ void cp_commit()  { asm volatile("cp.async.commit_group;"); }
__device__ __forceinline__ void cp_wait_1()  { asm volatile("cp.async.wait_group 1;" ::: "memory"); }
__device__ __forceinline__ void cp_wait_0()  { asm volatile("cp.async.wait_group 0;" ::: "memory"); }

// ---------------- kernel 1: weight cast + bias fold + state/flag reset ----------------
__global__ void k_prep(const float* __restrict__ Wih, const float* __restrict__ Whh,
                       const float* __restrict__ bih, const float* __restrict__ bhh) {
    size_t i = (size_t)blockIdx.x * blockDim.x + threadIdx.x;
    size_t stride = (size_t)gridDim.x * blockDim.x;
    const size_t N2 = (size_t)NT_ * G_ * H_;
    const size_t N1 = (size_t)NT_ * G_ * E_;
    for (size_t j = i; j < N2; j += stride) {
        g_Whh[j] = __float2bfloat16(Whh[j]);
        if (j < N1)               g_Wih[j]  = __float2bfloat16(Wih[j]);
        if (j < (size_t)NT_ * G_) g_bias[j] = bih[j] + bhh[j];
        if (j < (size_t)B_ * H_)  g_h[0][j] = __float2bfloat16(0.f);
        if (j < 64 * 32)          g_flags[j] = 0u;
    }
}

// ---------------- kernel 2: embedding gather -> bf16 [S][B][E] ----------------
__global__ void k_gather(const int* __restrict__ tokens, const float* __restrict__ emb) {
    size_t i = (size_t)blockIdx.x * blockDim.x + threadIdx.x;
    size_t stride = (size_t)gridDim.x * blockDim.x;
    const size_t N = (size_t)S_ * B_ * E_;
    for (size_t j = i; j < N; j += stride) {
        size_t t = j / ((size_t)B_ * E_);
        size_t r = j % ((size_t)B_ * E_);
        size_t b = r / E_;
        size_t e = r % E_;
        int tok = tokens[b * S_ + t];
        g_Xbf[j] = __float2bfloat16(emb[(size_t)tok * E_ + e]);
    }
}

// ---------------- kernel 3: x-projection  Xp[t] = x_t @ W_ih[tag_t]^T + bias ----------------
// Output written in recur-CTA-local layout: [t][cc][b][q*16+j].
__global__ __launch_bounds__(256) void k_xproj(const int* __restrict__ tags) {
    __shared__ char sbuf[36864];
    __shared__ float bias_s[64];
    __nv_bfloat16* As[2] = { (__nv_bfloat16*)sbuf,           (__nv_bfloat16*)(sbuf + 9216)  };
    __nv_bfloat16* Ws[2] = { (__nv_bfloat16*)(sbuf + 18432), (__nv_bfloat16*)(sbuf + 27648) };
    float* Cs = (float*)sbuf;

    const int t   = blockIdx.y;
    const int n0  = blockIdx.x * 64;
    const int tid = threadIdx.x;
    const int tag = tags[t];
    if (tid < 64) bias_s[tid] = g_bias[tag * G_ + n0 + tid];

    const __nv_bfloat16* Ag = g_Xbf + (size_t)t * B_ * E_;
    const __nv_bfloat16* Wg = g_Wih + (size_t)tag * G_ * E_ + (size_t)n0 * E_;

    const int r  = tid >> 4;
    const int cg = tid & 15;
    const int wid = tid >> 5, wm = wid >> 1, wn = wid & 1;

    wmma::fragment<wmma::accumulator, 16, 16, 16, float> acc0, acc1;
    wmma::fill_fragment(acc0, 0.f);
    wmma::fill_fragment(acc1, 0.f);

    uint2 ra[4], rw[4];
    auto loadregs = [&](int k0) {
#pragma unroll
        for (int i2 = 0; i2 < 4; i2++) {
            ra[i2] = *(const uint2*)(Ag + (size_t)(r + 16 * i2) * E_ + k0 + 4 * cg);
            rw[i2] = *(const uint2*)(Wg + (size_t)(r + 16 * i2) * E_ + k0 + 4 * cg);
        }
    };
    auto storeregs = [&](int p) {
#pragma unroll
        for (int i2 = 0; i2 < 4; i2++) {
            *(uint2*)(As[p] + (r + 16 * i2) * 72 + 4 * cg) = ra[i2];
            *(uint2*)(Ws[p] + (r + 16 * i2) * 72 + 4 * cg) = rw[i2];
        }
    };

    loadregs(0); storeregs(0);
#pragma unroll 1
    for (int it = 0; it < 8; it++) {
        int p = it & 1;
        __syncthreads();
        if (it < 7) loadregs((it + 1) * 64);
#pragma unroll
        for (int ks = 0; ks < 4; ks++) {
            wmma::fragment<wmma::matrix_a, 16, 16, 16, __nv_bfloat16, wmma::row_major> af;
            wmma::fragment<wmma::matrix_b, 16, 16, 16, __nv_bfloat16, wmma::col_major> bf0, bf1;
            wmma::load_matrix_sync(af,  As[p] + wm * 16 * 72 + ks * 16, 72);
            wmma::load_matrix_sync(bf0, Ws[p] + (wn * 32) * 72 + ks * 16, 72);
            wmma::load_matrix_sync(bf1, Ws[p] + (wn * 32 + 16) * 72 + ks * 16, 72);
            wmma::mma_sync(acc0, af, bf0, acc0);
            wmma::mma_sync(acc1, af, bf1, acc1);
        }
        if (it < 7) { __syncthreads(); storeregs(p ^ 1); }
    }
    __syncthreads();
    wmma::store_matrix_sync(Cs + wm * 16 * 68 + wn * 32,      acc0, 68, wmma::mem_row_major);
    wmma::store_matrix_sync(Cs + wm * 16 * 68 + wn * 32 + 16, acc1, 68, wmma::mem_row_major);
    __syncthreads();

    // Remapped output: gate n = n0 + c;  q = n>>10 (const per tile), cc = (n&1023)>>4, j = n&15.
    const int b  = tid >> 2;
    const int c0 = (tid & 3) * 16;
    const int q  = n0 >> 10;
    const int cc = ((n0 & 1023) >> 4) + (tid & 3);
    float* Out = g_Xp + ((((size_t)t * 64 + cc) * 64 + b) * 64) + q * 16;
#pragma unroll
    for (int u = 0; u < 4; u++) {
        int c = c0 + u * 4;
        float4 v;
        v.x = Cs[b * 68 + c + 0] + bias_s[c + 0];
        v.y = Cs[b * 68 + c + 1] + bias_s[c + 1];
        v.z = Cs[b * 68 + c + 2] + bias_s[c + 2];
        v.w = Cs[b * 68 + c + 3] + bias_s[c + 3];
        *(float4*)(Out + u * 4) = v;
    }
}

// ---------------- kernel 4: persistent recurrent scan (v4) ----------------
// 64 CTAs; CTA c owns h-cols [16c,16c+16) => 64 gate rows (4 strips of 16: i,f,g,o).
// W tile resident in smem (prefetched during previous epilogue). h streams L2->SMEM
// double-buffered. NEW: per-thread per-chunk flag acquire fused into the h copy
// (one flag per thread), chunk-order rotation per CTA, accumulators initialized
// directly from Xp (no epilogue adds), reduced barriers.
//
// Dynamic smem layout (bytes):
//   [0,      139264)  W_s   8 chunks x (64 x 136 bf16)
//   [139264, 174080)  h_s   2 x 17408      -- buf0 aliased as Cs after mma
//   [174080, 190464)  xp_s  (64 x 64 f32)
//   [190464, 194560)  c_s   (1024 f32)
//   [194560, 196608)  tags_s (512 int)
#define CH_ELEMS 8704           // 64*136 bf16 per chunk
#define RECUR_SMEM 196608

__global__ __launch_bounds__(256) void k_recur(const int* __restrict__ tags) {
    extern __shared__ char sbuf[];
    __nv_bfloat16* W_s = (__nv_bfloat16*)sbuf;
    __nv_bfloat16* h_s[2] = { (__nv_bfloat16*)(sbuf + 139264),
                              (__nv_bfloat16*)(sbuf + 139264 + 17408) };
    float* Cs     = (float*)(sbuf + 139264);
    float* xp_s   = (float*)(sbuf + 174080);
    float* c_s    = (float*)(sbuf + 190464);
    int*   tags_s = (int*)(sbuf + 194560);

    const int cta = blockIdx.x;        // 0..63
    const int hc0 = cta * 16;
    const int tid = threadIdx.x;
    for (int i = tid; i < S_;   i += 256) tags_s[i] = tags[i];
    for (int i = tid; i < 1024; i += 256) c_s[i] = 0.f;
    __syncthreads();

    const int rb  = tid >> 4;          // 0..15
    const int cg  = tid & 15;          // 0..15 (8 bf16 -> 128 cols per chunk)
    const int wid = tid >> 5, wm = wid >> 1, wn = wid & 1;
    const int rot = cta & 7;           // chunk-order rotation: spread producer deps
    const int fsub = cg >> 1;          // this thread's producer within a chunk

    // Prefetch full W tile for a step (physical chunk order).
    auto issueW = [&](int tag) {
        const __nv_bfloat16* Wg = g_Whh + (size_t)tag * G_ * H_;
#pragma unroll
        for (int c = 0; c < 8; c++) {
#pragma unroll
            for (int i2 = 0; i2 < 4; i2++)   // gate strip i2, local row rb
                cp_async16_cg(W_s + c * CH_ELEMS + (i2 * 16 + rb) * 136 + 8 * cg,
                              Wg + (size_t)(i2 * 1024 + hc0 + rb) * H_ + c * 128 + 8 * cg);
            cp_commit();
        }
    };
    // Acquire this thread's producer flag for physical chunk, then stream its h slice.
    auto pollIssueH = [&](const __nv_bfloat16* hin, int phys, int p, int t) {
        const unsigned* fp = &g_flags[(8 * phys + fsub) * 32];
        while (ld_acquire(fp) < (unsigned)t) { }
#pragma unroll
        for (int i2 = 0; i2 < 4; i2++)       // batch rows rb+16*i2
            cp_async16_cg(h_s[p] + (rb + 16 * i2) * 136 + 8 * cg,
                          hin + (size_t)(rb + 16 * i2) * H_ + phys * 128 + 8 * cg);
        cp_commit();
    };

    issueW(tags_s[0]);                  // W for step 0 in flight before the scan

    for (int t = 0; t < S_; t++) {
        // 1) Xp[t] slice: contiguous 16KB, own commit group
        {
            const float* src = g_Xp + (((size_t)t * 64 + cta) * 64) * 64 + tid * 16;
            float* dst = xp_s + tid * 16;
            cp_async16_cg(dst,      src);
            cp_async16_cg(dst + 4,  src + 4);
            cp_async16_cg(dst + 8,  src + 8);
            cp_async16_cg(dst + 12, src + 12);
            cp_commit();
        }

        const __nv_bfloat16* hin = g_h[t & 1];

        wmma::fragment<wmma::accumulator, 16, 16, 16, float> acc0, acc1;

        // 2) GEMM M=64 x N=64 x K=1024; per-chunk flag-gated h streaming, W resident
        pollIssueH(hin, rot, 0, t);
#pragma unroll
        for (int k = 0; k < 8; k++) {
            if (k < 7) { pollIssueH(hin, (k + 1 + rot) & 7, (k + 1) & 1, t); cp_wait_1(); }
            else       { cp_wait_0(); }
            __syncthreads();
            if (k == 0) {   // init accumulators from Xp (xp group completed by wait above)
                wmma::load_matrix_sync(acc0, xp_s + wm * 16 * 64 + wn * 32,      64, wmma::mem_row_major);
                wmma::load_matrix_sync(acc1, xp_s + wm * 16 * 64 + wn * 32 + 16, 64, wmma::mem_row_major);
            }
            const __nv_bfloat16* hb = h_s[k & 1];
            const __nv_bfloat16* wb = W_s + ((k + rot) & 7) * CH_ELEMS;
#pragma unroll
            for (int ks = 0; ks < 8; ks++) {
                wmma::fragment<wmma::matrix_a, 16, 16, 16, __nv_bfloat16, wmma::row_major> af;
                wmma::fragment<wmma::matrix_b, 16, 16, 16, __nv_bfloat16, wmma::col_major> bf0, bf1;
                wmma::load_matrix_sync(af,  hb + wm * 16 * 136 + ks * 16, 136);
                wmma::load_matrix_sync(bf0, wb + (wn * 32) * 136 + ks * 16, 136);
                wmma::load_matrix_sync(bf1, wb + (wn * 32 + 16) * 136 + ks * 16, 136);
                wmma::mma_sync(acc0, af, bf0, acc0);
                wmma::mma_sync(acc1, af, bf1, acc1);
            }
        }
        // own mma(7) read h_s[1] only; Cs aliases h_s[0] -> store needs no barrier
        wmma::store_matrix_sync(Cs + wm * 16 * 68 + wn * 32,      acc0, 68, wmma::mem_row_major);
        wmma::store_matrix_sync(Cs + wm * 16 * 68 + wn * 32 + 16, acc1, 68, wmma::mem_row_major);
        __syncthreads();    // all mma done (W_s free) + Cs visible to all threads

        // 3) next step's W prefetch overlaps epilogue + next flag waits
        if (t + 1 < S_) issueW(tags_s[t + 1]);

        // 4) gate math + state update (Cs already includes Xp)
        __nv_bfloat16* hout = g_h[(t + 1) & 1];
#pragma unroll
        for (int u = 0; u < 4; u++) {
            int idx = tid + 256 * u;
            int b = idx >> 4, j = idx & 15;
            float pi = Cs[b * 68 + j];
            float pf = Cs[b * 68 + 16 + j];
            float pg = Cs[b * 68 + 32 + j];
            float po = Cs[b * 68 + 48 + j];
            float ii = 1.f / (1.f + __expf(-pi));
            float ff = 1.f / (1.f + __expf(-pf));
            float gg = tanhf(pg);
            float oo = 1.f / (1.f + __expf(-po));
            float c  = ff * c_s[idx] + ii * gg;
            c_s[idx] = c;
            float h  = oo * tanhf(c);
            hout[(size_t)b * H_ + hc0 + j] = __float2bfloat16(h);
            if (t == S_ - 1) g_hf[(size_t)b * H_ + hc0 + j] = h;
        }
        __syncthreads();    // all h stores issued before release
        if (tid == 0) st_release(&g_flags[cta * 32], (unsigned)(t + 1));
    }
}

// ---------------- kernel 5: MLP head ----------------
__global__ __launch_bounds__(256) void k_mlp(const float* __restrict__ W1, const float* __restrict__ b1,
                                             const float* __restrict__ W2, const float* __restrict__ b2,
                                             float* __restrict__ out) {
    const int b = blockIdx.x;
    __shared__ float hs[H_];
    __shared__ float hid[DFF_];
    __shared__ float red[8];
    const int tid = threadIdx.x;
    for (int i = tid; i < H_; i += 256) hs[i] = g_hf[(size_t)b * H_ + i];
    __syncthreads();
    const int wid = tid >> 5, lane = tid & 31;
    for (int j = wid; j < DFF_; j += 8) {
        float s = 0.f;
        for (int k = lane; k < H_; k += 32) s += hs[k] * W1[(size_t)j * H_ + k];
#pragma unroll
        for (int o = 16; o; o >>= 1) s += __shfl_xor_sync(0xffffffffu, s, o);
        if (lane == 0) hid[j] = fmaxf(s + b1[j], 0.f);
    }
    __syncthreads();
    float v = hid[tid] * W2[tid];
#pragma unroll
    for (int o = 16; o; o >>= 1) v += __shfl_xor_sync(0xffffffffu, v, o);
    if (lane == 0) red[wid] = v;
    __syncthreads();
    if (tid == 0) {
        float z = b2[0];
#pragma unroll
        for (int i = 0; i < 8; i++) z += red[i];
        out[b] = 1.f / (1.f + expf(-z));
    }
}

// ---------------- launch ----------------
extern "C" void kernel_launch(void* const* d_in, const int* in_sizes, int n_in,
                              void* d_out, int out_size) {
    const int*   tokens = (const int*)d_in[0];
    const int*   tags   = (const int*)d_in[1];
    const float* emb    = (const float*)d_in[2];
    const float* Wih    = (const float*)d_in[3];
    const float* Whh    = (const float*)d_in[4];
    const float* bih    = (const float*)d_in[5];
    const float* bhh    = (const float*)d_in[6];
    const float* W1     = (const float*)d_in[7];
    const float* b1     = (const float*)d_in[8];
    const float* W2     = (const float*)d_in[9];
    const float* b2     = (const float*)d_in[10];
    float* out = (float*)d_out;

    cudaFuncSetAttribute(k_recur, cudaFuncAttributeMaxDynamicSharedMemorySize, RECUR_SMEM);

    k_prep<<<2048, 256>>>(Wih, Whh, bih, bhh);
    k_gather<<<2048, 256>>>(tokens, emb);
    k_xproj<<<dim3(64, 512), 256>>>(tags);
    k_recur<<<64, 256, RECUR_SMEM>>>(tags);
    k_mlp<<<64, 256>>>(W1, b1, W2, b2, out);
}

// round 15
// speedup vs baseline: 1.1542x; 1.1542x over previous
#include <cuda_runtime.h>
#include <cuda_bf16.h>
#include <mma.h>
#include <cstdint>
#include <cstddef>

using namespace nvcuda;

#define V_   50000
#define E_   512
#define H_   1024
#define S_   512
#define B_   64
#define NT_  13
#define G_   4096   // 4*H
#define DFF_ 256

// ---------------- static device scratch (no allocations allowed) ----------------
__device__ __nv_bfloat16 g_Wih[(size_t)NT_ * G_ * E_];   // bf16 input weights
__device__ __nv_bfloat16 g_Whh[(size_t)NT_ * G_ * H_];   // bf16 recurrent weights
__device__ float         g_bias[NT_ * G_];               // b_ih + b_hh
__device__ __nv_bfloat16 g_Xbf[(size_t)S_ * B_ * E_];    // gathered embeddings, bf16
// Xp layout: [t][cc][b][64]  (cc = recur CTA = h-col group; 64 cols = q*16+j, q=i/f/g/o)
__device__ float         g_Xp[(size_t)S_ * 64 * B_ * 64];
__device__ __nv_bfloat16 g_h[2][B_ * H_];                // double-buffered hidden state
__device__ float         g_hf[B_ * H_];                  // final hidden, fp32 for MLP
__device__ unsigned      g_flags[64 * 32];               // per-CTA step flags (128B padded)

// ---------------- helpers ----------------
__device__ __forceinline__ unsigned ld_acquire(const unsigned* p) {
    unsigned v;
    asm volatile("ld.acquire.gpu.u32 %0, [%1];" : "=r"(v) : "l"(p) : "memory");
    return v;
}
__device__ __forceinline__ void st_release(unsigned* p, unsigned v) {
    asm volatile("st.release.gpu.u32 [%0], %1;" :: "l"(p), "r"(v) : "memory");
}
// L2-only (cg) async copy: avoids stale-L1 hazards on cross-SM h traffic and L1 pollution.
__device__ __forceinline__ void cp_async16_cg(void* dst_smem, const void* src) {
    unsigned d = (unsigned)__cvta_generic_to_shared(dst_smem);
    asm volatile("cp.async.cg.shared.global [%0], [%1], 16;" :: "r"(d), "l"(src));
}
__device__ __forceinline__ void cp_commit()  { asm volatile("cp.async.commit_group;"); }
__device__ __forceinline__ void cp_wait_1()  { asm volatile("cp.async.wait_group 1;" ::: "memory"); }
__device__ __forceinline__ void cp_wait_0()  { asm volatile("cp.async.wait_group 0;" ::: "memory"); }
// MUFU.TANH-based activations (sm_75+ tanh.approx): ~1 MUFU op each
__device__ __forceinline__ float tanh_f(float x) {
    float y; asm("tanh.approx.f32 %0, %1;" : "=f"(y) : "f"(x)); return y;
}
__device__ __forceinline__ float sigm_f(float x) {
    return 0.5f * tanh_f(0.5f * x) + 0.5f;
}

// ---------------- kernel 1: weight cast + bias fold + state/flag reset ----------------
__global__ void k_prep(const float* __restrict__ Wih, const float* __restrict__ Whh,
                       const float* __restrict__ bih, const float* __restrict__ bhh) {
    size_t i = (size_t)blockIdx.x * blockDim.x + threadIdx.x;
    size_t stride = (size_t)gridDim.x * blockDim.x;
    const size_t N2 = (size_t)NT_ * G_ * H_;
    const size_t N1 = (size_t)NT_ * G_ * E_;
    for (size_t j = i; j < N2; j += stride) {
        g_Whh[j] = __float2bfloat16(Whh[j]);
        if (j < N1)               g_Wih[j]  = __float2bfloat16(Wih[j]);
        if (j < (size_t)NT_ * G_) g_bias[j] = bih[j] + bhh[j];
        if (j < (size_t)B_ * H_)  g_h[0][j] = __float2bfloat16(0.f);
        if (j < 64 * 32)          g_flags[j] = 0u;
    }
}

// ---------------- kernel 2: embedding gather -> bf16 [S][B][E] ----------------
__global__ void k_gather(const int* __restrict__ tokens, const float* __restrict__ emb) {
    size_t i = (size_t)blockIdx.x * blockDim.x + threadIdx.x;
    size_t stride = (size_t)gridDim.x * blockDim.x;
    const size_t N = (size_t)S_ * B_ * E_;
    for (size_t j = i; j < N; j += stride) {
        size_t t = j / ((size_t)B_ * E_);
        size_t r = j % ((size_t)B_ * E_);
        size_t b = r / E_;
        size_t e = r % E_;
        int tok = tokens[b * S_ + t];
        g_Xbf[j] = __float2bfloat16(emb[(size_t)tok * E_ + e]);
    }
}

// ---------------- kernel 3: x-projection  Xp[t] = x_t @ W_ih[tag_t]^T + bias ----------------
// Output written in recur-CTA-local layout: [t][cc][b][q*16+j].
__global__ __launch_bounds__(256) void k_xproj(const int* __restrict__ tags) {
    __shared__ char sbuf[36864];
    __shared__ float bias_s[64];
    __nv_bfloat16* As[2] = { (__nv_bfloat16*)sbuf,           (__nv_bfloat16*)(sbuf + 9216)  };
    __nv_bfloat16* Ws[2] = { (__nv_bfloat16*)(sbuf + 18432), (__nv_bfloat16*)(sbuf + 27648) };
    float* Cs = (float*)sbuf;

    const int t   = blockIdx.y;
    const int n0  = blockIdx.x * 64;
    const int tid = threadIdx.x;
    const int tag = tags[t];
    if (tid < 64) bias_s[tid] = g_bias[tag * G_ + n0 + tid];

    const __nv_bfloat16* Ag = g_Xbf + (size_t)t * B_ * E_;
    const __nv_bfloat16* Wg = g_Wih + (size_t)tag * G_ * E_ + (size_t)n0 * E_;

    const int r  = tid >> 4;
    const int cg = tid & 15;
    const int wid = tid >> 5, wm = wid >> 1, wn = wid & 1;

    wmma::fragment<wmma::accumulator, 16, 16, 16, float> acc0, acc1;
    wmma::fill_fragment(acc0, 0.f);
    wmma::fill_fragment(acc1, 0.f);

    uint2 ra[4], rw[4];
    auto loadregs = [&](int k0) {
#pragma unroll
        for (int i2 = 0; i2 < 4; i2++) {
            ra[i2] = *(const uint2*)(Ag + (size_t)(r + 16 * i2) * E_ + k0 + 4 * cg);
            rw[i2] = *(const uint2*)(Wg + (size_t)(r + 16 * i2) * E_ + k0 + 4 * cg);
        }
    };
    auto storeregs = [&](int p) {
#pragma unroll
        for (int i2 = 0; i2 < 4; i2++) {
            *(uint2*)(As[p] + (r + 16 * i2) * 72 + 4 * cg) = ra[i2];
            *(uint2*)(Ws[p] + (r + 16 * i2) * 72 + 4 * cg) = rw[i2];
        }
    };

    loadregs(0); storeregs(0);
#pragma unroll 1
    for (int it = 0; it < 8; it++) {
        int p = it & 1;
        __syncthreads();
        if (it < 7) loadregs((it + 1) * 64);
#pragma unroll
        for (int ks = 0; ks < 4; ks++) {
            wmma::fragment<wmma::matrix_a, 16, 16, 16, __nv_bfloat16, wmma::row_major> af;
            wmma::fragment<wmma::matrix_b, 16, 16, 16, __nv_bfloat16, wmma::col_major> bf0, bf1;
            wmma::load_matrix_sync(af,  As[p] + wm * 16 * 72 + ks * 16, 72);
            wmma::load_matrix_sync(bf0, Ws[p] + (wn * 32) * 72 + ks * 16, 72);
            wmma::load_matrix_sync(bf1, Ws[p] + (wn * 32 + 16) * 72 + ks * 16, 72);
            wmma::mma_sync(acc0, af, bf0, acc0);
            wmma::mma_sync(acc1, af, bf1, acc1);
        }
        if (it < 7) { __syncthreads(); storeregs(p ^ 1); }
    }
    __syncthreads();
    wmma::store_matrix_sync(Cs + wm * 16 * 68 + wn * 32,      acc0, 68, wmma::mem_row_major);
    wmma::store_matrix_sync(Cs + wm * 16 * 68 + wn * 32 + 16, acc1, 68, wmma::mem_row_major);
    __syncthreads();

    // Remapped output: gate n = n0 + c;  q = n>>10 (const per tile), cc = (n&1023)>>4, j = n&15.
    const int b  = tid >> 2;
    const int c0 = (tid & 3) * 16;
    const int q  = n0 >> 10;
    const int cc = ((n0 & 1023) >> 4) + (tid & 3);
    float* Out = g_Xp + ((((size_t)t * 64 + cc) * 64 + b) * 64) + q * 16;
#pragma unroll
    for (int u = 0; u < 4; u++) {
        int c = c0 + u * 4;
        float4 v;
        v.x = Cs[b * 68 + c + 0] + bias_s[c + 0];
        v.y = Cs[b * 68 + c + 1] + bias_s[c + 1];
        v.z = Cs[b * 68 + c + 2] + bias_s[c + 2];
        v.w = Cs[b * 68 + c + 3] + bias_s[c + 3];
        *(float4*)(Out + u * 4) = v;
    }
}

// ---------------- kernel 4: persistent recurrent scan (v5) ----------------
// 64 CTAs x 512 threads (16 warps); CTA c owns h-cols [16c,16c+16) => 64 gate rows.
// Warp (wm,wn) computes a 16x16 tile of the 64x64 gates GEMM (M=batch, N=gates, K=1024).
// Round-9 sync protocol (single coarse 64-thread acquire per step). W resident in smem,
// prefetched AFTER the flag release (off the global critical path). h double-buffered
// via cp.async.cg. Accumulators initialized from Xp. MUFU tanh/sigmoid epilogue.
//
// Dynamic smem layout (bytes):
//   [0,      139264)  W_s   8 chunks x (64 x 136 bf16)
//   [139264, 174080)  h_s   2 x 17408      -- buf0 aliased as Cs after mma
//   [174080, 190464)  xp_s  (64 x 64 f32)
//   [190464, 194560)  c_s   (1024 f32)
//   [194560, 196608)  tags_s (512 int)
#define CH_ELEMS 8704           // 64*136 bf16 per chunk
#define RECUR_SMEM 196608

__global__ __launch_bounds__(512) void k_recur(const int* __restrict__ tags) {
    extern __shared__ char sbuf[];
    __nv_bfloat16* W_s = (__nv_bfloat16*)sbuf;
    __nv_bfloat16* h_s[2] = { (__nv_bfloat16*)(sbuf + 139264),
                              (__nv_bfloat16*)(sbuf + 139264 + 17408) };
    float* Cs     = (float*)(sbuf + 139264);
    float* xp_s   = (float*)(sbuf + 174080);
    float* c_s    = (float*)(sbuf + 190464);
    int*   tags_s = (int*)(sbuf + 194560);

    const int cta = blockIdx.x;        // 0..63
    const int hc0 = cta * 16;
    const int tid = threadIdx.x;
    for (int i = tid; i < S_;   i += 512) tags_s[i] = tags[i];
    for (int i = tid; i < 1024; i += 512) c_s[i] = 0.f;
    __syncthreads();

    const int wid = tid >> 5, wm = wid >> 2, wn = wid & 3;   // 4x4 warp grid, 16x16 tiles
    const int hr  = tid >> 3;          // 0..63  copy row
    const int hc  = tid & 7;           // 0..7   copy col group (8 bf16; two groups/row)
    const int wrow = (hr >> 4) * 1024 + hc0 + (hr & 15);     // W source row for dst row hr

    // Prefetch full W tile for a step (8 chunks = 8 commit groups).
    auto issueW = [&](int tag) {
        const __nv_bfloat16* Wg = g_Whh + (size_t)tag * G_ * H_;
#pragma unroll
        for (int c = 0; c < 8; c++) {
            cp_async16_cg(W_s + c * CH_ELEMS + hr * 136 + hc * 8,
                          Wg + (size_t)wrow * H_ + c * 128 + hc * 8);
            cp_async16_cg(W_s + c * CH_ELEMS + hr * 136 + hc * 8 + 64,
                          Wg + (size_t)wrow * H_ + c * 128 + hc * 8 + 64);
            cp_commit();
        }
    };
    auto issueH = [&](const __nv_bfloat16* hin, int c, int p) {
        cp_async16_cg(h_s[p] + hr * 136 + hc * 8,
                      hin + (size_t)hr * H_ + c * 128 + hc * 8);
        cp_async16_cg(h_s[p] + hr * 136 + hc * 8 + 64,
                      hin + (size_t)hr * H_ + c * 128 + hc * 8 + 64);
        cp_commit();
    };

    issueW(tags_s[0]);                  // W for step 0 in flight before the scan

    for (int t = 0; t < S_; t++) {
        // 1) Xp[t] slice: contiguous 16KB, part of the first h commit group's wait set
        {
            const float* src = g_Xp + (((size_t)t * 64 + cta) * 64) * 64 + tid * 8;
            cp_async16_cg(xp_s + tid * 8,     src);
            cp_async16_cg(xp_s + tid * 8 + 4, src + 4);
            cp_commit();
        }

        // 2) one coarse acquire: all producers published step t-1
        if (tid < 64) {
            const unsigned* fp = &g_flags[tid * 32];
            while (ld_acquire(fp) < (unsigned)t) { }
        }
        __syncthreads();

        const __nv_bfloat16* hin = g_h[t & 1];

        // 3) GEMM M=64 x N=64 x K=1024; h double-buffered, W resident
        wmma::fragment<wmma::accumulator, 16, 16, 16, float> acc;

        issueH(hin, 0, 0);
#pragma unroll
        for (int k = 0; k < 8; k++) {
            if (k < 7) { issueH(hin, k + 1, (k + 1) & 1); cp_wait_1(); }
            else       { cp_wait_0(); }
            __syncthreads();
            if (k == 0) {   // init accumulator from Xp (xp group completed by wait above)
                wmma::load_matrix_sync(acc, xp_s + wm * 16 * 64 + wn * 16, 64, wmma::mem_row_major);
            }
            const __nv_bfloat16* hb = h_s[k & 1];
            const __nv_bfloat16* wb = W_s + k * CH_ELEMS;
#pragma unroll
            for (int ks = 0; ks < 8; ks++) {
                wmma::fragment<wmma::matrix_a, 16, 16, 16, __nv_bfloat16, wmma::row_major> af;
                wmma::fragment<wmma::matrix_b, 16, 16, 16, __nv_bfloat16, wmma::col_major> bf;
                wmma::load_matrix_sync(af, hb + wm * 16 * 136 + ks * 16, 136);
                wmma::load_matrix_sync(bf, wb + (wn * 16) * 136 + ks * 16, 136);
                wmma::mma_sync(acc, af, bf, acc);
            }
        }
        // own mma(7) read h_s[1] only; Cs aliases h_s[0] -> store needs no barrier
        wmma::store_matrix_sync(Cs + wm * 16 * 68 + wn * 16, acc, 68, wmma::mem_row_major);
        __syncthreads();    // all mma done (W_s free) + Cs visible to all threads

        // 4) gate math + state update (Cs already includes Xp); MUFU activations
        __nv_bfloat16* hout = g_h[(t + 1) & 1];
#pragma unroll
        for (int u = 0; u < 2; u++) {
            int idx = tid + 512 * u;
            int b = idx >> 4, j = idx & 15;
            float pi = Cs[b * 68 + j];
            float pf = Cs[b * 68 + 16 + j];
            float pg = Cs[b * 68 + 32 + j];
            float po = Cs[b * 68 + 48 + j];
            float ii = sigm_f(pi);
            float ff = sigm_f(pf);
            float gg = tanh_f(pg);
            float oo = sigm_f(po);
            float c  = ff * c_s[idx] + ii * gg;
            c_s[idx] = c;
            float h  = oo * tanh_f(c);
            hout[(size_t)b * H_ + hc0 + j] = __float2bfloat16(h);
            if (t == S_ - 1) g_hf[(size_t)b * H_ + hc0 + j] = h;
        }
        __syncthreads();    // all h stores done before release

        // 5) release FIRST (global critical path), then local W prefetch for t+1
        if (tid == 0) st_release(&g_flags[cta * 32], (unsigned)(t + 1));
        if (t + 1 < S_) issueW(tags_s[t + 1]);
    }
}

// ---------------- kernel 5: MLP head ----------------
__global__ __launch_bounds__(256) void k_mlp(const float* __restrict__ W1, const float* __restrict__ b1,
                                             const float* __restrict__ W2, const float* __restrict__ b2,
                                             float* __restrict__ out) {
    const int b = blockIdx.x;
    __shared__ float hs[H_];
    __shared__ float hid[DFF_];
    __shared__ float red[8];
    const int tid = threadIdx.x;
    for (int i = tid; i < H_; i += 256) hs[i] = g_hf[(size_t)b * H_ + i];
    __syncthreads();
    const int wid = tid >> 5, lane = tid & 31;
    for (int j = wid; j < DFF_; j += 8) {
        float s = 0.f;
        for (int k = lane; k < H_; k += 32) s += hs[k] * W1[(size_t)j * H_ + k];
#pragma unroll
        for (int o = 16; o; o >>= 1) s += __shfl_xor_sync(0xffffffffu, s, o);
        if (lane == 0) hid[j] = fmaxf(s + b1[j], 0.f);
    }
    __syncthreads();
    float v = hid[tid] * W2[tid];
#pragma unroll
    for (int o = 16; o; o >>= 1) v += __shfl_xor_sync(0xffffffffu, v, o);
    if (lane == 0) red[wid] = v;
    __syncthreads();
    if (tid == 0) {
        float z = b2[0];
#pragma unroll
        for (int i = 0; i < 8; i++) z += red[i];
        out[b] = 1.f / (1.f + expf(-z));
    }
}

// ---------------- launch ----------------
extern "C" void kernel_launch(void* const* d_in, const int* in_sizes, int n_in,
                              void* d_out, int out_size) {
    const int*   tokens = (const int*)d_in[0];
    const int*   tags   = (const int*)d_in[1];
    const float* emb    = (const float*)d_in[2];
    const float* Wih    = (const float*)d_in[3];
    const float* Whh    = (const float*)d_in[4];
    const float* bih    = (const float*)d_in[5];
    const float* bhh    = (const float*)d_in[6];
    const float* W1     = (const float*)d_in[7];
    const float* b1     = (const float*)d_in[8];
    const float* W2     = (const float*)d_in[9];
    const float* b2     = (const float*)d_in[10];
    float* out = (float*)d_out;

    cudaFuncSetAttribute(k_recur, cudaFuncAttributeMaxDynamicSharedMemorySize, RECUR_SMEM);

    k_prep<<<2048, 256>>>(Wih, Whh, bih, bhh);
    k_gather<<<2048, 256>>>(tokens, emb);
    k_xproj<<<dim3(64, 512), 256>>>(tags);
    k_recur<<<64, 512, RECUR_SMEM>>>(tags);
    k_mlp<<<64, 256>>>(W1, b1, W2, b2, out);
}